// round 2
// baseline (speedup 1.0000x reference)
#include <cuda_runtime.h>
#include <math.h>

// ---------------- problem constants ----------------
#define LTOK 32768      // B * D*H*W
#define CDIM 192
#define NWIN 64
#define NHD  6
#define NTOK 512
#define HDD  32

// ---------------- device scratch (static, allocation-free) ----------------
__device__ float g_xn[LTOK * CDIM];
__device__ float g_q[NWIN * NHD * NTOK * HDD];
__device__ float g_k[NWIN * NHD * NTOK * HDD];
__device__ float g_v[NWIN * NHD * NTOK * HDD];
__device__ float g_attnout[LTOK * CDIM];
__device__ float g_h1[LTOK * 64];
__device__ float g_h2[LTOK * CDIM];
__device__ float g_x2[LTOK * CDIM];
__device__ float g_x2n[LTOK * CDIM];
__device__ float g_mh[LTOK * 768];
__device__ float g_w1t[27 * 192 * 64];
__device__ float g_w2t[27 * 64 * 192];
__device__ float g_bias[NHD * NTOK * NTOK];
__device__ float g_pp[128 * CDIM];
__device__ float g_ca[CDIM];

__device__ __forceinline__ float gelu_exact(float x) {
    return 0.5f * x * (1.0f + erff(x * 0.70710678118654752440f));
}

// ---------------- LayerNorm: one warp per row (C=192 = 32*6) ----------------
__global__ void ln_kernel(const float* __restrict__ x, const float* __restrict__ g,
                          const float* __restrict__ b, float* __restrict__ out) {
    int row  = blockIdx.x * blockDim.y + threadIdx.y;
    int lane = threadIdx.x;
    const float* xr = x + (size_t)row * CDIM;
    float v[6]; float s = 0.f, ss = 0.f;
#pragma unroll
    for (int i = 0; i < 6; i++) { v[i] = xr[lane + 32*i]; s += v[i]; ss += v[i]*v[i]; }
#pragma unroll
    for (int o = 16; o > 0; o >>= 1) {
        s  += __shfl_xor_sync(0xffffffffu, s, o);
        ss += __shfl_xor_sync(0xffffffffu, ss, o);
    }
    float mean = s * (1.f/192.f);
    float var  = ss * (1.f/192.f) - mean*mean;
    float rstd = rsqrtf(var + 1e-5f);
    float* orow = out + (size_t)row * CDIM;
#pragma unroll
    for (int i = 0; i < 6; i++)
        orow[lane + 32*i] = (v[i]-mean)*rstd*g[lane + 32*i] + b[lane + 32*i];
}

// ---------------- conv weight transpose: [co][ci][27] -> [kk][ci][co] ----------------
__global__ void wtrans_kernel(const float* __restrict__ w1, const float* __restrict__ w2) {
    int idx = blockIdx.x * 256 + threadIdx.x;
    if (idx < 64*192*27) {
        int co = idx / (192*27);
        int ci = (idx / 27) % 192;
        int kk = idx % 27;
        g_w1t[(kk*192 + ci)*64 + co] = w1[idx];
    }
    if (idx < 192*64*27) {
        int co = idx / (64*27);
        int ci = (idx / 27) % 64;
        int kk = idx % 27;
        g_w2t[(kk*64 + ci)*192 + co] = w2[idx];
    }
}

// ---------------- relative-position bias gather: g_bias[h][n][m] ----------------
__global__ void bias_kernel(const int* __restrict__ rpi, const float* __restrict__ rpb) {
    int idx = blockIdx.x * 256 + threadIdx.x;
    if (idx >= NHD * NTOK * NTOK) return;
    int h  = idx / (NTOK*NTOK);
    int nm = idx % (NTOK*NTOK);
    g_bias[idx] = rpb[rpi[nm]*NHD + h];
}

// ---------------- generic 64x64x16 smem GEMM: out = A[M,K] @ W[N,K]^T + bias ----------------
// EPI: 0 plain, 1 qkv-scatter, 2 proj+residual, 3 gelu, 4 final add
template<int EPI>
__global__ __launch_bounds__(256)
void gemm_kernel(const float* __restrict__ A, const float* __restrict__ Wt,
                 const float* __restrict__ bias, float* __restrict__ out,
                 int M, int Nn, int K, const float* __restrict__ aux0) {
    __shared__ __align__(16) float As[16][68];
    __shared__ __align__(16) float Bs[16][68];
    const int m0 = blockIdx.x * 64;
    const int n0 = blockIdx.y * 64;
    const int tid = threadIdx.x;
    const int tr = tid >> 4, tc = tid & 15;
    float acc[4][4] = {};
    for (int k0 = 0; k0 < K; k0 += 16) {
#pragma unroll
        for (int t = 0; t < 4; t++) {
            int idx = tid + t*256;
            int mm = idx >> 4, kk = idx & 15;
            As[kk][mm] = A [(size_t)(m0+mm)*K + (k0+kk)];
            Bs[kk][mm] = Wt[(size_t)(n0+mm)*K + (k0+kk)];
        }
        __syncthreads();
#pragma unroll
        for (int kk = 0; kk < 16; kk++) {
            float4 a = *(const float4*)&As[kk][tr*4];
            float4 b = *(const float4*)&Bs[kk][tc*4];
            acc[0][0]+=a.x*b.x; acc[0][1]+=a.x*b.y; acc[0][2]+=a.x*b.z; acc[0][3]+=a.x*b.w;
            acc[1][0]+=a.y*b.x; acc[1][1]+=a.y*b.y; acc[1][2]+=a.y*b.z; acc[1][3]+=a.y*b.w;
            acc[2][0]+=a.z*b.x; acc[2][1]+=a.z*b.y; acc[2][2]+=a.z*b.z; acc[2][3]+=a.z*b.w;
            acc[3][0]+=a.w*b.x; acc[3][1]+=a.w*b.y; acc[3][2]+=a.w*b.z; acc[3][3]+=a.w*b.w;
        }
        __syncthreads();
    }
#pragma unroll
    for (int i = 0; i < 4; i++) {
        int m = m0 + tr*4 + i;
#pragma unroll
        for (int j = 0; j < 4; j++) {
            int n = n0 + tc*4 + j;
            float v = acc[i][j] + bias[n];
            if (EPI == 0) {
                out[(size_t)m*Nn + n] = v;
            } else if (EPI == 1) {
                // m is spatial token l; scatter into window layout q/k/v
                int which = n / 192, c = n % 192;
                int head = c >> 5, hd = c & 31;
                int d = m >> 12, h = (m >> 6) & 63, w = m & 63;
                int wi = ((h >> 3) << 3) | (w >> 3);
                int nt = (d << 6) | ((h & 7) << 3) | (w & 7);
                size_t dst = ((size_t)((wi*NHD + head)*NTOK + nt))*HDD + hd;
                if (which == 0)      g_q[dst] = v * 0.17677669529663687f; // HD^-0.5
                else if (which == 1) g_k[dst] = v;
                else                 g_v[dst] = v;
            } else if (EPI == 2) {
                // m is window-layout token (wi*512+nt); reverse to spatial + residual + conv branch
                int wi = m >> 9, nt = m & 511;
                int d = nt >> 6;
                int h = ((wi >> 3) << 3) | ((nt >> 3) & 7);
                int w = ((wi & 7) << 3) | (nt & 7);
                size_t l = ((size_t)d << 12) | (h << 6) | w;
                size_t o = l*CDIM + n;
                g_x2[o] = aux0[o] + v + g_h2[o] * g_ca[n] * 0.01f;
            } else if (EPI == 3) {
                out[(size_t)m*Nn + n] = gelu_exact(v);
            } else { // EPI == 4
                out[(size_t)m*Nn + n] = g_x2[(size_t)m*CDIM + n] + v;
            }
        }
    }
}

// ---------------- 3x3x3 conv as 27 shifted GEMMs over one (d,h)-row of 64 w ----------------
template<bool DO_GELU>
__global__ __launch_bounds__(256)
void conv_kernel(const float* __restrict__ in, const float* __restrict__ wt,
                 const float* __restrict__ bias, float* __restrict__ out,
                 int CIN, int COUT) {
    __shared__ __align__(16) float As[16][68];
    __shared__ __align__(16) float Bs[16][68];
    const int row = blockIdx.x;             // 0..511 -> (d, h)
    const int co0 = blockIdx.y * 64;
    const int d = row >> 6, h = row & 63;
    const int l0 = row * 64;                // token at w=0
    const int tid = threadIdx.x;
    const int tr = tid >> 4, tc = tid & 15;
    float acc[4][4] = {};
    for (int kk = 0; kk < 27; kk++) {
        int dd = kk/9 - 1, dh = (kk/3)%3 - 1, dw = kk%3 - 1;
        bool rowvalid = ((unsigned)(d+dd) < 8u) && ((unsigned)(h+dh) < 64u);
        int off = dd*4096 + dh*64 + dw;
        const float* wk = wt + (size_t)kk * CIN * COUT;
        for (int c0 = 0; c0 < CIN; c0 += 16) {
#pragma unroll
            for (int t = 0; t < 4; t++) {
                int idx = tid + t*256;
                int pos = idx >> 4, ci = idx & 15;
                float val = 0.f;
                int ww = pos + dw;
                if (rowvalid && (unsigned)ww < 64u)
                    val = in[(size_t)(l0 + pos + off)*CIN + c0 + ci];
                As[ci][pos] = val;
            }
#pragma unroll
            for (int t = 0; t < 4; t++) {
                int idx = tid + t*256;
                int ci = idx >> 6, co = idx & 63;
                Bs[ci][co] = wk[(size_t)(c0+ci)*COUT + co0 + co];
            }
            __syncthreads();
#pragma unroll
            for (int ci = 0; ci < 16; ci++) {
                float4 a = *(const float4*)&As[ci][tr*4];
                float4 b = *(const float4*)&Bs[ci][tc*4];
                acc[0][0]+=a.x*b.x; acc[0][1]+=a.x*b.y; acc[0][2]+=a.x*b.z; acc[0][3]+=a.x*b.w;
                acc[1][0]+=a.y*b.x; acc[1][1]+=a.y*b.y; acc[1][2]+=a.y*b.z; acc[1][3]+=a.y*b.w;
                acc[2][0]+=a.z*b.x; acc[2][1]+=a.z*b.y; acc[2][2]+=a.z*b.z; acc[2][3]+=a.z*b.w;
                acc[3][0]+=a.w*b.x; acc[3][1]+=a.w*b.y; acc[3][2]+=a.w*b.z; acc[3][3]+=a.w*b.w;
            }
            __syncthreads();
        }
    }
#pragma unroll
    for (int i = 0; i < 4; i++) {
        int pos = tr*4 + i;
#pragma unroll
        for (int j = 0; j < 4; j++) {
            int co = co0 + tc*4 + j;
            float v = acc[i][j] + bias[co];
            if (DO_GELU) v = gelu_exact(v);
            out[(size_t)(l0 + pos)*COUT + co] = v;
        }
    }
}

// ---------------- global avg pool (stage 1): 128 blocks x 256 rows ----------------
__global__ void pool_kernel(const float* __restrict__ h2, float* __restrict__ partial) {
    int b = blockIdx.x, c = threadIdx.x;
    float s = 0.f;
    const float* base = h2 + (size_t)b * 256 * CDIM + c;
    for (int r = 0; r < 256; r++) s += base[(size_t)r * CDIM];
    partial[b*CDIM + c] = s;
}

// ---------------- channel attention (stage 2): single block ----------------
__global__ void ca_kernel(const float* __restrict__ partial,
                          const float* __restrict__ ca1w, const float* __restrict__ ca1b,
                          const float* __restrict__ ca2w, const float* __restrict__ ca2b) {
    __shared__ float pooled[CDIM];
    __shared__ float t6[6];
    int c = threadIdx.x;
    float s = 0.f;
    for (int b = 0; b < 128; b++) s += partial[b*CDIM + c];
    pooled[c] = s * (1.f/32768.f);
    __syncthreads();
    if (c < 6) {
        float a = ca1b[c];
        for (int i = 0; i < CDIM; i++) a += pooled[i] * ca1w[c*CDIM + i];
        t6[c] = fmaxf(a, 0.f);
    }
    __syncthreads();
    float a = ca2b[c];
#pragma unroll
    for (int j = 0; j < 6; j++) a += t6[j] * ca2w[c*6 + j];
    g_ca[c] = 1.f / (1.f + __expf(-a));
}

// ---------------- window attention: one block per (window, head), K/V in smem ----------------
__global__ __launch_bounds__(512)
void attn_kernel() {
    extern __shared__ float sm[];
    float* sk = sm;
    float* sv = sm + NTOK*HDD;
    int wi = blockIdx.x / NHD, hh = blockIdx.x % NHD;
    size_t base = ((size_t)(wi*NHD + hh)) * NTOK * HDD;
    int tid = threadIdx.x;
    const float4* k4 = (const float4*)(g_k + base);
    const float4* v4 = (const float4*)(g_v + base);
    for (int i = tid; i < NTOK*HDD/4; i += 512) {
        ((float4*)sk)[i] = k4[i];
        ((float4*)sv)[i] = v4[i];
    }
    __syncthreads();
    const int r = tid;   // one query row per thread
    float qr[32];
    const float4* q4 = (const float4*)(g_q + base + (size_t)r * HDD);
#pragma unroll
    for (int i = 0; i < 8; i++) {
        float4 t = q4[i];
        qr[4*i] = t.x; qr[4*i+1] = t.y; qr[4*i+2] = t.z; qr[4*i+3] = t.w;
    }
    const float* brow = g_bias + ((size_t)hh*NTOK + r) * NTOK;
    float mmax = -1e30f, lsum = 0.f;
    float o[32];
#pragma unroll
    for (int i = 0; i < 32; i++) o[i] = 0.f;
    for (int j4 = 0; j4 < NTOK; j4 += 4) {
        float4 bq = *(const float4*)&brow[j4];
        float bvv[4] = {bq.x, bq.y, bq.z, bq.w};
#pragma unroll
        for (int jj = 0; jj < 4; jj++) {
            int j = j4 + jj;
            const float4* kr = (const float4*)(sk + j*HDD);
            float s = bvv[jj];
#pragma unroll
            for (int i = 0; i < 8; i++) {
                float4 kv = kr[i];
                s += qr[4*i]*kv.x + qr[4*i+1]*kv.y + qr[4*i+2]*kv.z + qr[4*i+3]*kv.w;
            }
            const float4* vr = (const float4*)(sv + j*HDD);
            if (s <= mmax) {
                float p = __expf(s - mmax);
                lsum += p;
#pragma unroll
                for (int i = 0; i < 8; i++) {
                    float4 vv = vr[i];
                    o[4*i]   += p*vv.x; o[4*i+1] += p*vv.y;
                    o[4*i+2] += p*vv.z; o[4*i+3] += p*vv.w;
                }
            } else {
                float sc = __expf(mmax - s);
                mmax = s;
                lsum = lsum*sc + 1.f;
#pragma unroll
                for (int i = 0; i < 8; i++) {
                    float4 vv = vr[i];
                    o[4*i]   = o[4*i]*sc   + vv.x;
                    o[4*i+1] = o[4*i+1]*sc + vv.y;
                    o[4*i+2] = o[4*i+2]*sc + vv.z;
                    o[4*i+3] = o[4*i+3]*sc + vv.w;
                }
            }
        }
    }
    float inv = 1.f / lsum;
    float* dst = g_attnout + ((size_t)(wi*NTOK + r))*CDIM + hh*HDD;
#pragma unroll
    for (int i = 0; i < 32; i++) dst[i] = o[i]*inv;
}

// ---------------- launch ----------------
extern "C" void kernel_launch(void* const* d_in, const int* in_sizes, int n_in,
                              void* d_out, int out_size) {
    const float* x     = (const float*)d_in[0];
    const float* n1g   = (const float*)d_in[1];
    const float* n1b   = (const float*)d_in[2];
    const float* qkvw  = (const float*)d_in[3];
    const float* qkvb  = (const float*)d_in[4];
    const float* rpb   = (const float*)d_in[5];
    const float* projw = (const float*)d_in[6];
    const float* projb = (const float*)d_in[7];
    const float* c1w   = (const float*)d_in[8];
    const float* c1b   = (const float*)d_in[9];
    const float* c2w   = (const float*)d_in[10];
    const float* c2b   = (const float*)d_in[11];
    const float* ca1w  = (const float*)d_in[12];
    const float* ca1b  = (const float*)d_in[13];
    const float* ca2w  = (const float*)d_in[14];
    const float* ca2b  = (const float*)d_in[15];
    const float* n2g   = (const float*)d_in[16];
    const float* n2b   = (const float*)d_in[17];
    const float* fc1w  = (const float*)d_in[18];
    const float* fc1b  = (const float*)d_in[19];
    const float* fc2w  = (const float*)d_in[20];
    const float* fc2b  = (const float*)d_in[21];
    const int*   rpi   = (const int*)d_in[22];
    float* out = (float*)d_out;

    float *p_xn, *p_h1, *p_h2, *p_x2, *p_x2n, *p_mh, *p_pp, *p_attnout, *p_w1t, *p_w2t;
    cudaGetSymbolAddress((void**)&p_xn,      g_xn);
    cudaGetSymbolAddress((void**)&p_h1,      g_h1);
    cudaGetSymbolAddress((void**)&p_h2,      g_h2);
    cudaGetSymbolAddress((void**)&p_x2,      g_x2);
    cudaGetSymbolAddress((void**)&p_x2n,     g_x2n);
    cudaGetSymbolAddress((void**)&p_mh,      g_mh);
    cudaGetSymbolAddress((void**)&p_pp,      g_pp);
    cudaGetSymbolAddress((void**)&p_attnout, g_attnout);
    cudaGetSymbolAddress((void**)&p_w1t,     g_w1t);
    cudaGetSymbolAddress((void**)&p_w2t,     g_w2t);

    cudaFuncSetAttribute(attn_kernel, cudaFuncAttributeMaxDynamicSharedMemorySize,
                         2 * NTOK * HDD * (int)sizeof(float));

    // 1) LN1
    ln_kernel<<<4096, dim3(32, 8)>>>(x, n1g, n1b, p_xn);
    // 2) one-shot transposes / gathers
    wtrans_kernel<<<1296, 256>>>(c1w, c2w);
    bias_kernel<<<(NHD*NTOK*NTOK + 255)/256, 256>>>(rpi, rpb);
    // 3) QKV projection -> window layout
    gemm_kernel<1><<<dim3(512, 9), 256>>>(p_xn, qkvw, qkvb, nullptr, LTOK, 576, CDIM, nullptr);
    // 4) conv branch
    conv_kernel<true ><<<dim3(512, 1), 256>>>(p_xn, p_w1t, c1b, p_h1, 192, 64);
    conv_kernel<false><<<dim3(512, 3), 256>>>(p_h1, p_w2t, c2b, p_h2, 64, 192);
    pool_kernel<<<128, CDIM>>>(p_h2, p_pp);
    ca_kernel<<<1, CDIM>>>(p_pp, ca1w, ca1b, ca2w, ca2b);
    // 5) window attention
    attn_kernel<<<NWIN * NHD, 512, 2 * NTOK * HDD * (int)sizeof(float)>>>();
    // 6) proj + window reverse + residual + conv*0.01 -> g_x2
    gemm_kernel<2><<<dim3(512, 3), 256>>>(p_attnout, projw, projb, nullptr, LTOK, CDIM, CDIM, x);
    // 7) LN2 + MLP
    ln_kernel<<<4096, dim3(32, 8)>>>(p_x2, n2g, n2b, p_x2n);
    gemm_kernel<3><<<dim3(512, 12), 256>>>(p_x2n, fc1w, fc1b, p_mh, LTOK, 768, CDIM, nullptr);
    gemm_kernel<4><<<dim3(512, 3), 256>>>(p_mh, fc2w, fc2b, out, LTOK, CDIM, 768, nullptr);
}